// round 13
// baseline (speedup 1.0000x reference)
#include <cuda_runtime.h>
#include <cuda_bf16.h>
#include <cstdint>
#include <math.h>

// ============================================================================
// InfoNCE loss, GB300 (sm_103a, PTX target sm_103 -> legacy bf16 HMMA path)
//  loss = -log(P / (P + N)),
//  P = sum(exp(zi.ziT / T))  [symmetric: off-diag tiles weighted x2]
//  N = sum(exp(zi.zjT / T))
//
//  Round-13: gemm identical to round-5/12 (structural optimum ~403 TF/s).
//  Norm rewritten two-pass (asm-volatile loads, ~24 regs -> 100% occupancy,
//  pass-2 reload is L2-hot). Finish widened to 1024 threads.
// ============================================================================

#define N_ROWS   8192
#define DDIM     512
#define BM       128
#define BN       128
#define NTHREADS 256
#define NKCH     8            // K chunks of 64 elems (128B rows)

#define ROW_TILES 64
#define NEG_TILES (ROW_TILES * ROW_TILES)              // 4096
#define DIAG_TILES ROW_TILES                           // 64
#define UPPER_TILES (ROW_TILES * (ROW_TILES - 1) / 2)  // 2016 (w=2)
#define TOTAL_TILES (NEG_TILES + DIAG_TILES + UPPER_TILES) // 6176

// exp(x/T) = ex2(x * (1/T) * log2(e)), T = 0.1
#define EXP_SCALE 14.4269504088896340736f

__device__ __nv_bfloat16 g_zi[(size_t)N_ROWS * DDIM];
__device__ __nv_bfloat16 g_zj[(size_t)N_ROWS * DDIM];
__device__ double g_partials[TOTAL_TILES];

// ---------------------------------------------------------------------------
__device__ __forceinline__ uint32_t smem_u32(const void* p) {
    uint32_t a;
    asm("{ .reg .u64 t; cvta.to.shared.u64 t, %1; cvt.u32.u64 %0, t; }" : "=r"(a) : "l"(p));
    return a;
}

// asm-volatile 16B load: not CSE-able -> two-pass norm stays two-pass
__device__ __forceinline__ float4 ldg128v(const float* p) {
    float4 v;
    asm volatile("ld.global.ca.v4.f32 {%0,%1,%2,%3}, [%4];"
                 : "=f"(v.x), "=f"(v.y), "=f"(v.z), "=f"(v.w) : "l"(p));
    return v;
}

#define CP_ASYNC16(dst_u32, src_ptr) \
    asm volatile("cp.async.cg.shared.global [%0], [%1], 16;" \
                 :: "r"(dst_u32), "l"(src_ptr) : "memory")
#define CP_COMMIT() asm volatile("cp.async.commit_group;" ::: "memory")
#define CP_WAIT(n)  asm volatile("cp.async.wait_group %0;" :: "n"(n) : "memory")

__device__ __forceinline__ void ldmx4(uint32_t* r, uint32_t addr) {
    asm volatile("ldmatrix.sync.aligned.m8n8.x4.shared.b16 {%0,%1,%2,%3}, [%4];"
                 : "=r"(r[0]), "=r"(r[1]), "=r"(r[2]), "=r"(r[3]) : "r"(addr));
}

__device__ __forceinline__ void mma_bf16(float* d, const uint32_t* a,
                                         const uint32_t* b) {
    asm volatile(
        "mma.sync.aligned.m16n8k16.row.col.f32.bf16.bf16.f32 "
        "{%0,%1,%2,%3}, {%4,%5,%6,%7}, {%8,%9}, {%0,%1,%2,%3};"
        : "+f"(d[0]), "+f"(d[1]), "+f"(d[2]), "+f"(d[3])
        : "r"(a[0]), "r"(a[1]), "r"(a[2]), "r"(a[3]), "r"(b[0]), "r"(b[1]));
}

// smem: 3 stages of (A 16KB + B 16KB); rows of 128B, swizzle colb^((r&7)<<4)
#define STAGE_BYTES    32768
#define SMEM_B_OFF     16384
#define SMEM_DYN_TOTAL (3 * STAGE_BYTES)   // 98304 per CTA; 2 CTAs = 192KB/SM

// ---------------------------------------------------------------------------
// 1) normalize + bf16 cast, TWO-PASS (low regs -> 100% occupancy).
//    One warp per row; 8 rows per 256-thread block; grid 2048.
//    Pass 1: load + sum-squares (values discarded). Pass 2: reload (L2-hot),
//    scale, cast, store.
// ---------------------------------------------------------------------------
__global__ void __launch_bounds__(256) norm_kernel(const float* __restrict__ zi,
                                                   const float* __restrict__ zj) {
    int row  = blockIdx.x * 8 + (threadIdx.x >> 5);
    int lane = threadIdx.x & 31;
    bool is_i = row < N_ROWS;
    int r = is_i ? row : row - N_ROWS;
    const float* src = (is_i ? zi : zj) + (size_t)r * DDIM;
    __nv_bfloat16* dst = (is_i ? g_zi : g_zj) + (size_t)r * DDIM;

    // pass 1: sum of squares
    float ss = 0.0f;
    #pragma unroll
    for (int j = 0; j < 4; j++) {
        float4 v = ldg128v(src + 4 * lane + 128 * j);
        ss += v.x * v.x + v.y * v.y + v.z * v.z + v.w * v.w;
    }
    #pragma unroll
    for (int o = 16; o; o >>= 1) ss += __shfl_xor_sync(0xFFFFFFFFu, ss, o);
    float inv = 1.0f / fmaxf(sqrtf(ss), 1e-12f);

    // pass 2: reload (L1/L2 hit), scale, cast, store
    #pragma unroll
    for (int j = 0; j < 4; j++) {
        float4 v = ldg128v(src + 4 * lane + 128 * j);
        __nv_bfloat162 p0 = __floats2bfloat162_rn(v.x * inv, v.y * inv);
        __nv_bfloat162 p1 = __floats2bfloat162_rn(v.z * inv, v.w * inv);
        uint2 pack;
        pack.x = *reinterpret_cast<uint32_t*>(&p0);
        pack.y = *reinterpret_cast<uint32_t*>(&p1);
        ((uint2*)dst)[lane + 32 * j] = pack;
    }
}

// ---------------------------------------------------------------------------
// 2) fused GEMM + exp-sum. 8 warps = 4(M) x 2(N); warp tile 32x64.
//    3-stage pipeline, one barrier per chunk. (round-5, unchanged)
// ---------------------------------------------------------------------------
__global__ void __launch_bounds__(NTHREADS, 2) gemm_kernel() {
    extern __shared__ char smem[];
    uint32_t sb = smem_u32(smem);
    int tid  = threadIdx.x;
    int lane = tid & 31;
    int wid  = tid >> 5;
    int warp_m = wid & 3;
    int warp_n = wid >> 2;

    // ---- tile decode: neg / diag / upper(x2) ----
    int b = blockIdx.x;
    int rt, ct, weight;
    const __nv_bfloat16* Bmat;
    if (b < NEG_TILES) {
        rt = b >> 6; ct = b & 63; weight = 1; Bmat = g_zj;
    } else if (b < NEG_TILES + DIAG_TILES) {
        rt = ct = b - NEG_TILES; weight = 1; Bmat = g_zi;
    } else {
        int k = b - NEG_TILES - DIAG_TILES;
        int r = 0, rowlen = ROW_TILES - 1;
        while (k >= rowlen) { k -= rowlen; rowlen--; r++; }
        rt = r; ct = r + 1 + k; weight = 2; Bmat = g_zi;
    }
    const char* Ag = (const char*)(g_zi + (size_t)rt * BM * DDIM);
    const char* Bg = (const char*)(Bmat + (size_t)ct * BN * DDIM);

    // ---- accumulators ----
    float acc[2][8][4];
    #pragma unroll
    for (int mt = 0; mt < 2; mt++)
        #pragma unroll
        for (int nt = 0; nt < 8; nt++)
            #pragma unroll
            for (int i = 0; i < 4; i++) acc[mt][nt][i] = 0.0f;

    // ---- ldmatrix per-thread address components ----
    int a_row0 = warp_m * 32 + (lane & 15);
    int a_row1 = a_row0 + 16;
    uint32_t a_rb0 = a_row0 * 128, a_xm0 = (a_row0 & 7) << 4;
    uint32_t a_rb1 = a_row1 * 128, a_xm1 = (a_row1 & 7) << 4;
    uint32_t a_csub = (lane >> 4) << 4;

    uint32_t b_rb[4], b_xm[4];
    #pragma unroll
    for (int ntp = 0; ntp < 4; ntp++) {
        int rb = warp_n * 64 + ntp * 16 + ((lane >> 4) << 3) + (lane & 7);
        b_rb[ntp] = rb * 128;
        b_xm[ntp] = (rb & 7) << 4;
    }
    uint32_t b_csub = ((lane >> 3) & 1) << 4;

    // ---- staging: 8 x 16B chunks per thread per stage (A 4 + B 4) ----
    #define STAGE(buf, kc) do {                                                 \
        uint32_t abase = sb + (buf) * STAGE_BYTES;                              \
        uint32_t bbase = abase + SMEM_B_OFF;                                    \
        const char* agp = Ag + (size_t)(kc) * 128;                              \
        const char* bgp = Bg + (size_t)(kc) * 128;                              \
        _Pragma("unroll")                                                       \
        for (int j = 0; j < 4; j++) {                                           \
            int i = tid + j * NTHREADS;                                         \
            int r = i >> 3, s = i & 7;                                          \
            uint32_t dst = abase + r * 128 + ((s * 16) ^ ((r & 7) << 4));       \
            CP_ASYNC16(dst, agp + (size_t)r * (DDIM * 2) + s * 16);             \
        }                                                                       \
        _Pragma("unroll")                                                       \
        for (int j = 0; j < 4; j++) {                                           \
            int i = tid + j * NTHREADS;                                         \
            int r = i >> 3, s = i & 7;                                          \
            uint32_t dst = bbase + r * 128 + ((s * 16) ^ ((r & 7) << 4));       \
            CP_ASYNC16(dst, bgp + (size_t)r * (DDIM * 2) + s * 16);             \
        }                                                                       \
    } while (0)

    STAGE(0, 0); CP_COMMIT();
    STAGE(1, 1); CP_COMMIT();

    int buf = 0;
    #pragma unroll 1
    for (int kc = 0; kc < NKCH; kc++) {
        if (kc < NKCH - 1) CP_WAIT(1); else CP_WAIT(0);
        __syncthreads();   // stage kc visible; stage (kc-1)%3 fully drained
        if (kc + 2 < NKCH) {
            int nb = buf + 2; if (nb >= 3) nb -= 3;
            STAGE(nb, kc + 2);
            CP_COMMIT();
        }

        uint32_t abase = sb + buf * STAGE_BYTES;
        uint32_t bbase = abase + SMEM_B_OFF;

        #pragma unroll
        for (int kk = 0; kk < 4; kk++) {
            uint32_t kb = kk * 32;
            uint32_t afr[2][4];
            ldmx4(afr[0], abase + a_rb0 + ((kb + a_csub) ^ a_xm0));
            ldmx4(afr[1], abase + a_rb1 + ((kb + a_csub) ^ a_xm1));
            uint32_t bfr[8][2];
            #pragma unroll
            for (int ntp = 0; ntp < 4; ntp++) {
                uint32_t r[4];
                ldmx4(r, bbase + b_rb[ntp] + ((kb + b_csub) ^ b_xm[ntp]));
                bfr[2 * ntp][0] = r[0];     bfr[2 * ntp][1] = r[1];
                bfr[2 * ntp + 1][0] = r[2]; bfr[2 * ntp + 1][1] = r[3];
            }
            #pragma unroll
            for (int mt = 0; mt < 2; mt++)
                #pragma unroll
                for (int nt = 0; nt < 8; nt++)
                    mma_bf16(acc[mt][nt], afr[mt], bfr[nt]);
        }
        buf++; if (buf >= 3) buf = 0;
    }
    #undef STAGE

    // ---- epilogue: fp32 ex2 exp-sum ----
    float ps0 = 0.0f, ps1 = 0.0f;
    #pragma unroll
    for (int mt = 0; mt < 2; mt++)
        #pragma unroll
        for (int nt = 0; nt < 8; nt++)
            #pragma unroll
            for (int i = 0; i < 4; i++) {
                float s = acc[mt][nt][i] * EXP_SCALE;
                float e;
                asm("ex2.approx.ftz.f32 %0, %1;" : "=f"(e) : "f"(s));
                if (i & 1) ps1 += e; else ps0 += e;
            }
    float psum = ps0 + ps1;
    #pragma unroll
    for (int o = 16; o; o >>= 1) psum += __shfl_xor_sync(0xFFFFFFFFu, psum, o);

    __shared__ float red[8];
    if (lane == 0) red[wid] = psum;
    __syncthreads();
    if (tid == 0) {
        double tot = 0.0;
        #pragma unroll
        for (int w = 0; w < 8; w++) tot += (double)red[w];
        g_partials[blockIdx.x] = tot * (double)weight;
    }
}

// ---------------------------------------------------------------------------
// 3) final reduction -> loss scalar (1024 threads)
// ---------------------------------------------------------------------------
__global__ void __launch_bounds__(1024) finish_kernel(float* __restrict__ out) {
    int t = threadIdx.x;
    double p = 0.0, n = 0.0;
    for (int i = t; i < TOTAL_TILES; i += 1024) {
        double v = g_partials[i];
        if (i < NEG_TILES) n += v; else p += v;
    }
    __shared__ double sp[1024], sn[1024];
    sp[t] = p; sn[t] = n;
    __syncthreads();
    for (int s = 512; s; s >>= 1) {
        if (t < s) { sp[t] += sp[t + s]; sn[t] += sn[t + s]; }
        __syncthreads();
    }
    if (t == 0) {
        double P = sp[0], N = sn[0];
        out[0] = (float)(-log(P / (N + P)));
    }
}

// ---------------------------------------------------------------------------
extern "C" void kernel_launch(void* const* d_in, const int* in_sizes, int n_in,
                              void* d_out, int out_size) {
    const float* zi = (const float*)d_in[0];
    const float* zj = (const float*)d_in[1];

    cudaFuncSetAttribute(gemm_kernel, cudaFuncAttributeMaxDynamicSharedMemorySize,
                         SMEM_DYN_TOTAL);

    norm_kernel<<<2 * N_ROWS / 8, 256>>>(zi, zj);
    gemm_kernel<<<TOTAL_TILES, NTHREADS, SMEM_DYN_TOTAL>>>();
    finish_kernel<<<1, 1024>>>((float*)d_out);
}

// round 14
// speedup vs baseline: 1.0301x; 1.0301x over previous
#include <cuda_runtime.h>
#include <cuda_bf16.h>
#include <cstdint>
#include <math.h>

// ============================================================================
// InfoNCE loss, GB300 (sm_103a, PTX target sm_103 -> legacy bf16 HMMA path)
//  loss = -log(P / (P + N)),
//  P = sum(exp(zi.ziT / T))  [symmetric: off-diag tiles weighted x2]
//  N = sum(exp(zi.zjT / T))
//
//  Round-14: round-5 kernel restored VERBATIM (best: 272.80us, reproduced
//  3x within 0.1us). 128x128 tile, 8 warps 4Mx2N, 2 CTAs/SM, 3-stage
//  cp.async pipeline, one __syncthreads per K-chunk, fp32 ex2 epilogue.
//  All structural alternatives empirically falsified in rounds 3-13.
// ============================================================================

#define N_ROWS   8192
#define DDIM     512
#define BM       128
#define BN       128
#define NTHREADS 256
#define NKCH     8            // K chunks of 64 elems (128B rows)

#define ROW_TILES 64
#define NEG_TILES (ROW_TILES * ROW_TILES)              // 4096
#define DIAG_TILES ROW_TILES                           // 64
#define UPPER_TILES (ROW_TILES * (ROW_TILES - 1) / 2)  // 2016 (w=2)
#define TOTAL_TILES (NEG_TILES + DIAG_TILES + UPPER_TILES) // 6176

// exp(x/T) = ex2(x * (1/T) * log2(e)), T = 0.1
#define EXP_SCALE 14.4269504088896340736f

__device__ __nv_bfloat16 g_zi[(size_t)N_ROWS * DDIM];
__device__ __nv_bfloat16 g_zj[(size_t)N_ROWS * DDIM];
__device__ double g_partials[TOTAL_TILES];

// ---------------------------------------------------------------------------
__device__ __forceinline__ uint32_t smem_u32(const void* p) {
    uint32_t a;
    asm("{ .reg .u64 t; cvta.to.shared.u64 t, %1; cvt.u32.u64 %0, t; }" : "=r"(a) : "l"(p));
    return a;
}

#define CP_ASYNC16(dst_u32, src_ptr) \
    asm volatile("cp.async.cg.shared.global [%0], [%1], 16;" \
                 :: "r"(dst_u32), "l"(src_ptr) : "memory")
#define CP_COMMIT() asm volatile("cp.async.commit_group;" ::: "memory")
#define CP_WAIT(n)  asm volatile("cp.async.wait_group %0;" :: "n"(n) : "memory")

__device__ __forceinline__ void ldmx4(uint32_t* r, uint32_t addr) {
    asm volatile("ldmatrix.sync.aligned.m8n8.x4.shared.b16 {%0,%1,%2,%3}, [%4];"
                 : "=r"(r[0]), "=r"(r[1]), "=r"(r[2]), "=r"(r[3]) : "r"(addr));
}

__device__ __forceinline__ void mma_bf16(float* d, const uint32_t* a,
                                         const uint32_t* b) {
    asm volatile(
        "mma.sync.aligned.m16n8k16.row.col.f32.bf16.bf16.f32 "
        "{%0,%1,%2,%3}, {%4,%5,%6,%7}, {%8,%9}, {%0,%1,%2,%3};"
        : "+f"(d[0]), "+f"(d[1]), "+f"(d[2]), "+f"(d[3])
        : "r"(a[0]), "r"(a[1]), "r"(a[2]), "r"(a[3]), "r"(b[0]), "r"(b[1]));
}

// smem: 3 stages of (A 16KB + B 16KB); rows of 128B, swizzle colb^((r&7)<<4)
#define STAGE_BYTES    32768
#define SMEM_B_OFF     16384
#define SMEM_DYN_TOTAL (3 * STAGE_BYTES)   // 98304 per CTA; 2 CTAs = 192KB/SM

// ---------------------------------------------------------------------------
// 1) normalize + bf16 cast. One warp per row; 8 rows per 256-thread block.
// ---------------------------------------------------------------------------
__global__ void __launch_bounds__(256) norm_kernel(const float* __restrict__ zi,
                                                   const float* __restrict__ zj) {
    int row  = blockIdx.x * 8 + (threadIdx.x >> 5);
    int lane = threadIdx.x & 31;
    bool is_i = row < N_ROWS;
    const float* src = is_i ? (zi + (size_t)row * DDIM)
                            : (zj + (size_t)(row - N_ROWS) * DDIM);
    __nv_bfloat16* dst = is_i ? (g_zi + (size_t)row * DDIM)
                              : (g_zj + (size_t)(row - N_ROWS) * DDIM);
    float4 v[4];
    float ss = 0.0f;
    #pragma unroll
    for (int j = 0; j < 4; j++) {
        v[j] = ((const float4*)src)[lane + 32 * j];
        ss += v[j].x * v[j].x + v[j].y * v[j].y + v[j].z * v[j].z + v[j].w * v[j].w;
    }
    #pragma unroll
    for (int o = 16; o; o >>= 1) ss += __shfl_xor_sync(0xFFFFFFFFu, ss, o);
    float inv = 1.0f / fmaxf(sqrtf(ss), 1e-12f);
    #pragma unroll
    for (int j = 0; j < 4; j++) {
        __nv_bfloat162 p0 = __floats2bfloat162_rn(v[j].x * inv, v[j].y * inv);
        __nv_bfloat162 p1 = __floats2bfloat162_rn(v[j].z * inv, v[j].w * inv);
        uint2 pack;
        pack.x = *reinterpret_cast<uint32_t*>(&p0);
        pack.y = *reinterpret_cast<uint32_t*>(&p1);
        ((uint2*)dst)[lane + 32 * j] = pack;
    }
}

// ---------------------------------------------------------------------------
// 2) fused GEMM + exp-sum. 8 warps = 4(M) x 2(N); warp tile 32x64.
//    3-stage pipeline, one barrier per chunk.
// ---------------------------------------------------------------------------
__global__ void __launch_bounds__(NTHREADS, 2) gemm_kernel() {
    extern __shared__ char smem[];
    uint32_t sb = smem_u32(smem);
    int tid  = threadIdx.x;
    int lane = tid & 31;
    int wid  = tid >> 5;
    int warp_m = wid & 3;
    int warp_n = wid >> 2;

    // ---- tile decode: neg / diag / upper(x2) ----
    int b = blockIdx.x;
    int rt, ct, weight;
    const __nv_bfloat16* Bmat;
    if (b < NEG_TILES) {
        rt = b >> 6; ct = b & 63; weight = 1; Bmat = g_zj;
    } else if (b < NEG_TILES + DIAG_TILES) {
        rt = ct = b - NEG_TILES; weight = 1; Bmat = g_zi;
    } else {
        int k = b - NEG_TILES - DIAG_TILES;
        int r = 0, rowlen = ROW_TILES - 1;
        while (k >= rowlen) { k -= rowlen; rowlen--; r++; }
        rt = r; ct = r + 1 + k; weight = 2; Bmat = g_zi;
    }
    const char* Ag = (const char*)(g_zi + (size_t)rt * BM * DDIM);
    const char* Bg = (const char*)(Bmat + (size_t)ct * BN * DDIM);

    // ---- accumulators ----
    float acc[2][8][4];
    #pragma unroll
    for (int mt = 0; mt < 2; mt++)
        #pragma unroll
        for (int nt = 0; nt < 8; nt++)
            #pragma unroll
            for (int i = 0; i < 4; i++) acc[mt][nt][i] = 0.0f;

    // ---- ldmatrix per-thread address components ----
    int a_row0 = warp_m * 32 + (lane & 15);
    int a_row1 = a_row0 + 16;
    uint32_t a_rb0 = a_row0 * 128, a_xm0 = (a_row0 & 7) << 4;
    uint32_t a_rb1 = a_row1 * 128, a_xm1 = (a_row1 & 7) << 4;
    uint32_t a_csub = (lane >> 4) << 4;

    uint32_t b_rb[4], b_xm[4];
    #pragma unroll
    for (int ntp = 0; ntp < 4; ntp++) {
        int rb = warp_n * 64 + ntp * 16 + ((lane >> 4) << 3) + (lane & 7);
        b_rb[ntp] = rb * 128;
        b_xm[ntp] = (rb & 7) << 4;
    }
    uint32_t b_csub = ((lane >> 3) & 1) << 4;

    // ---- staging: 8 x 16B chunks per thread per stage (A 4 + B 4) ----
    #define STAGE(buf, kc) do {                                                 \
        uint32_t abase = sb + (buf) * STAGE_BYTES;                              \
        uint32_t bbase = abase + SMEM_B_OFF;                                    \
        const char* agp = Ag + (size_t)(kc) * 128;                              \
        const char* bgp = Bg + (size_t)(kc) * 128;                              \
        _Pragma("unroll")                                                       \
        for (int j = 0; j < 4; j++) {                                           \
            int i = tid + j * NTHREADS;                                         \
            int r = i >> 3, s = i & 7;                                          \
            uint32_t dst = abase + r * 128 + ((s * 16) ^ ((r & 7) << 4));       \
            CP_ASYNC16(dst, agp + (size_t)r * (DDIM * 2) + s * 16);             \
        }                                                                       \
        _Pragma("unroll")                                                       \
        for (int j = 0; j < 4; j++) {                                           \
            int i = tid + j * NTHREADS;                                         \
            int r = i >> 3, s = i & 7;                                          \
            uint32_t dst = bbase + r * 128 + ((s * 16) ^ ((r & 7) << 4));       \
            CP_ASYNC16(dst, bgp + (size_t)r * (DDIM * 2) + s * 16);             \
        }                                                                       \
    } while (0)

    STAGE(0, 0); CP_COMMIT();
    STAGE(1, 1); CP_COMMIT();

    int buf = 0;
    #pragma unroll 1
    for (int kc = 0; kc < NKCH; kc++) {
        if (kc < NKCH - 1) CP_WAIT(1); else CP_WAIT(0);
        __syncthreads();   // stage kc visible; stage (kc-1)%3 fully drained
        if (kc + 2 < NKCH) {
            int nb = buf + 2; if (nb >= 3) nb -= 3;
            STAGE(nb, kc + 2);
            CP_COMMIT();
        }

        uint32_t abase = sb + buf * STAGE_BYTES;
        uint32_t bbase = abase + SMEM_B_OFF;

        #pragma unroll
        for (int kk = 0; kk < 4; kk++) {
            uint32_t kb = kk * 32;
            uint32_t afr[2][4];
            ldmx4(afr[0], abase + a_rb0 + ((kb + a_csub) ^ a_xm0));
            ldmx4(afr[1], abase + a_rb1 + ((kb + a_csub) ^ a_xm1));
            uint32_t bfr[8][2];
            #pragma unroll
            for (int ntp = 0; ntp < 4; ntp++) {
                uint32_t r[4];
                ldmx4(r, bbase + b_rb[ntp] + ((kb + b_csub) ^ b_xm[ntp]));
                bfr[2 * ntp][0] = r[0];     bfr[2 * ntp][1] = r[1];
                bfr[2 * ntp + 1][0] = r[2]; bfr[2 * ntp + 1][1] = r[3];
            }
            #pragma unroll
            for (int mt = 0; mt < 2; mt++)
                #pragma unroll
                for (int nt = 0; nt < 8; nt++)
                    mma_bf16(acc[mt][nt], afr[mt], bfr[nt]);
        }
        buf++; if (buf >= 3) buf = 0;
    }
    #undef STAGE

    // ---- epilogue: fp32 ex2 exp-sum ----
    float ps0 = 0.0f, ps1 = 0.0f;
    #pragma unroll
    for (int mt = 0; mt < 2; mt++)
        #pragma unroll
        for (int nt = 0; nt < 8; nt++)
            #pragma unroll
            for (int i = 0; i < 4; i++) {
                float s = acc[mt][nt][i] * EXP_SCALE;
                float e;
                asm("ex2.approx.ftz.f32 %0, %1;" : "=f"(e) : "f"(s));
                if (i & 1) ps1 += e; else ps0 += e;
            }
    float psum = ps0 + ps1;
    #pragma unroll
    for (int o = 16; o; o >>= 1) psum += __shfl_xor_sync(0xFFFFFFFFu, psum, o);

    __shared__ float red[8];
    if (lane == 0) red[wid] = psum;
    __syncthreads();
    if (tid == 0) {
        double tot = 0.0;
        #pragma unroll
        for (int w = 0; w < 8; w++) tot += (double)red[w];
        g_partials[blockIdx.x] = tot * (double)weight;
    }
}

// ---------------------------------------------------------------------------
// 3) final reduction -> loss scalar
// ---------------------------------------------------------------------------
__global__ void __launch_bounds__(256) finish_kernel(float* __restrict__ out) {
    int t = threadIdx.x;
    double p = 0.0, n = 0.0;
    for (int i = t; i < TOTAL_TILES; i += 256) {
        double v = g_partials[i];
        if (i < NEG_TILES) n += v; else p += v;
    }
    __shared__ double sp[256], sn[256];
    sp[t] = p; sn[t] = n;
    __syncthreads();
    for (int s = 128; s; s >>= 1) {
        if (t < s) { sp[t] += sp[t + s]; sn[t] += sn[t + s]; }
        __syncthreads();
    }
    if (t == 0) {
        double P = sp[0], N = sn[0];
        out[0] = (float)(-log(P / (N + P)));
    }
}

// ---------------------------------------------------------------------------
extern "C" void kernel_launch(void* const* d_in, const int* in_sizes, int n_in,
                              void* d_out, int out_size) {
    const float* zi = (const float*)d_in[0];
    const float* zj = (const float*)d_in[1];

    cudaFuncSetAttribute(gemm_kernel, cudaFuncAttributeMaxDynamicSharedMemorySize,
                         SMEM_DYN_TOTAL);

    norm_kernel<<<2 * N_ROWS / 8, 256>>>(zi, zj);
    gemm_kernel<<<TOTAL_TILES, NTHREADS, SMEM_DYN_TOTAL>>>();
    finish_kernel<<<1, 256>>>((float*)d_out);
}

// round 15
// speedup vs baseline: 1.1118x; 1.0794x over previous
#include <cuda_runtime.h>
#include <cuda_bf16.h>
#include <cstdint>
#include <math.h>

// ============================================================================
// InfoNCE loss, GB300 (sm_103a, PTX target sm_103 -> legacy bf16 HMMA path)
//  loss = -log(P / (P + N)),
//  P = sum(exp(zi.ziT / T))  [symmetric: off-diag tiles weighted x2]
//  N = sum(exp(zi.zjT / T))
//
//  Round-15: round-14 (= round-5) kernel with ONE change: per-chunk cp.async
//  staging split into 4 quarter-stages interleaved between each kstep's
//  LDSM batch and MMA batch. Smooths smem-crossbar demand (LDSM 384 + STS
//  128 = 512 cyc/kstep, matching the 512-cyc tensor floor) instead of a
//  512-cyc STS burst at chunk start that stalled chunk-start LDSMs.
// ============================================================================

#define N_ROWS   8192
#define DDIM     512
#define BM       128
#define BN       128
#define NTHREADS 256
#define NKCH     8            // K chunks of 64 elems (128B rows)

#define ROW_TILES 64
#define NEG_TILES (ROW_TILES * ROW_TILES)              // 4096
#define DIAG_TILES ROW_TILES                           // 64
#define UPPER_TILES (ROW_TILES * (ROW_TILES - 1) / 2)  // 2016 (w=2)
#define TOTAL_TILES (NEG_TILES + DIAG_TILES + UPPER_TILES) // 6176

// exp(x/T) = ex2(x * (1/T) * log2(e)), T = 0.1
#define EXP_SCALE 14.4269504088896340736f

__device__ __nv_bfloat16 g_zi[(size_t)N_ROWS * DDIM];
__device__ __nv_bfloat16 g_zj[(size_t)N_ROWS * DDIM];
__device__ double g_partials[TOTAL_TILES];

// ---------------------------------------------------------------------------
__device__ __forceinline__ uint32_t smem_u32(const void* p) {
    uint32_t a;
    asm("{ .reg .u64 t; cvta.to.shared.u64 t, %1; cvt.u32.u64 %0, t; }" : "=r"(a) : "l"(p));
    return a;
}

#define CP_ASYNC16(dst_u32, src_ptr) \
    asm volatile("cp.async.cg.shared.global [%0], [%1], 16;" \
                 :: "r"(dst_u32), "l"(src_ptr) : "memory")
#define CP_COMMIT() asm volatile("cp.async.commit_group;" ::: "memory")
#define CP_WAIT(n)  asm volatile("cp.async.wait_group %0;" :: "n"(n) : "memory")

__device__ __forceinline__ void ldmx4(uint32_t* r, uint32_t addr) {
    asm volatile("ldmatrix.sync.aligned.m8n8.x4.shared.b16 {%0,%1,%2,%3}, [%4];"
                 : "=r"(r[0]), "=r"(r[1]), "=r"(r[2]), "=r"(r[3]) : "r"(addr));
}

__device__ __forceinline__ void mma_bf16(float* d, const uint32_t* a,
                                         const uint32_t* b) {
    asm volatile(
        "mma.sync.aligned.m16n8k16.row.col.f32.bf16.bf16.f32 "
        "{%0,%1,%2,%3}, {%4,%5,%6,%7}, {%8,%9}, {%0,%1,%2,%3};"
        : "+f"(d[0]), "+f"(d[1]), "+f"(d[2]), "+f"(d[3])
        : "r"(a[0]), "r"(a[1]), "r"(a[2]), "r"(a[3]), "r"(b[0]), "r"(b[1]));
}

// smem: 3 stages of (A 16KB + B 16KB); rows of 128B, swizzle colb^((r&7)<<4)
#define STAGE_BYTES    32768
#define SMEM_B_OFF     16384
#define SMEM_DYN_TOTAL (3 * STAGE_BYTES)   // 98304 per CTA; 2 CTAs = 192KB/SM

// ---------------------------------------------------------------------------
// 1) normalize + bf16 cast. One warp per row; 8 rows per 256-thread block.
// ---------------------------------------------------------------------------
__global__ void __launch_bounds__(256) norm_kernel(const float* __restrict__ zi,
                                                   const float* __restrict__ zj) {
    int row  = blockIdx.x * 8 + (threadIdx.x >> 5);
    int lane = threadIdx.x & 31;
    bool is_i = row < N_ROWS;
    const float* src = is_i ? (zi + (size_t)row * DDIM)
                            : (zj + (size_t)(row - N_ROWS) * DDIM);
    __nv_bfloat16* dst = is_i ? (g_zi + (size_t)row * DDIM)
                              : (g_zj + (size_t)(row - N_ROWS) * DDIM);
    float4 v[4];
    float ss = 0.0f;
    #pragma unroll
    for (int j = 0; j < 4; j++) {
        v[j] = ((const float4*)src)[lane + 32 * j];
        ss += v[j].x * v[j].x + v[j].y * v[j].y + v[j].z * v[j].z + v[j].w * v[j].w;
    }
    #pragma unroll
    for (int o = 16; o; o >>= 1) ss += __shfl_xor_sync(0xFFFFFFFFu, ss, o);
    float inv = 1.0f / fmaxf(sqrtf(ss), 1e-12f);
    #pragma unroll
    for (int j = 0; j < 4; j++) {
        __nv_bfloat162 p0 = __floats2bfloat162_rn(v[j].x * inv, v[j].y * inv);
        __nv_bfloat162 p1 = __floats2bfloat162_rn(v[j].z * inv, v[j].w * inv);
        uint2 pack;
        pack.x = *reinterpret_cast<uint32_t*>(&p0);
        pack.y = *reinterpret_cast<uint32_t*>(&p1);
        ((uint2*)dst)[lane + 32 * j] = pack;
    }
}

// ---------------------------------------------------------------------------
// 2) fused GEMM + exp-sum. 8 warps = 4(M) x 2(N); warp tile 32x64.
//    3-stage pipeline, one barrier per chunk, staging spread across ksteps.
// ---------------------------------------------------------------------------
__global__ void __launch_bounds__(NTHREADS, 2) gemm_kernel() {
    extern __shared__ char smem[];
    uint32_t sb = smem_u32(smem);
    int tid  = threadIdx.x;
    int lane = tid & 31;
    int wid  = tid >> 5;
    int warp_m = wid & 3;
    int warp_n = wid >> 2;

    // ---- tile decode: neg / diag / upper(x2) ----
    int b = blockIdx.x;
    int rt, ct, weight;
    const __nv_bfloat16* Bmat;
    if (b < NEG_TILES) {
        rt = b >> 6; ct = b & 63; weight = 1; Bmat = g_zj;
    } else if (b < NEG_TILES + DIAG_TILES) {
        rt = ct = b - NEG_TILES; weight = 1; Bmat = g_zi;
    } else {
        int k = b - NEG_TILES - DIAG_TILES;
        int r = 0, rowlen = ROW_TILES - 1;
        while (k >= rowlen) { k -= rowlen; rowlen--; r++; }
        rt = r; ct = r + 1 + k; weight = 2; Bmat = g_zi;
    }
    const char* Ag = (const char*)(g_zi + (size_t)rt * BM * DDIM);
    const char* Bg = (const char*)(Bmat + (size_t)ct * BN * DDIM);

    // ---- accumulators ----
    float acc[2][8][4];
    #pragma unroll
    for (int mt = 0; mt < 2; mt++)
        #pragma unroll
        for (int nt = 0; nt < 8; nt++)
            #pragma unroll
            for (int i = 0; i < 4; i++) acc[mt][nt][i] = 0.0f;

    // ---- ldmatrix per-thread address components ----
    int a_row0 = warp_m * 32 + (lane & 15);
    int a_row1 = a_row0 + 16;
    uint32_t a_rb0 = a_row0 * 128, a_xm0 = (a_row0 & 7) << 4;
    uint32_t a_rb1 = a_row1 * 128, a_xm1 = (a_row1 & 7) << 4;
    uint32_t a_csub = (lane >> 4) << 4;

    uint32_t b_rb[4], b_xm[4];
    #pragma unroll
    for (int ntp = 0; ntp < 4; ntp++) {
        int rb = warp_n * 64 + ntp * 16 + ((lane >> 4) << 3) + (lane & 7);
        b_rb[ntp] = rb * 128;
        b_xm[ntp] = (rb & 7) << 4;
    }
    uint32_t b_csub = ((lane >> 3) & 1) << 4;

    // ---- per-thread staging coords (fixed across chunks) ----
    // chunk has 1024 16B segs per matrix; thread covers i = tid + q*256,
    // q in [0,4): r = i>>3 (row), s = i&7 (16B seg in 128B row).
    // full stage = all 4 quarters; quarter q issued inside kstep q.
    #define STAGE_Q(bufi, kc, q) do {                                           \
        uint32_t abase2 = sb + (bufi) * STAGE_BYTES;                            \
        uint32_t bbase2 = abase2 + SMEM_B_OFF;                                  \
        int i = tid + (q) * NTHREADS;                                           \
        int r = i >> 3, s = i & 7;                                              \
        uint32_t off = r * 128 + ((s * 16) ^ ((r & 7) << 4));                   \
        const char* agp = Ag + (size_t)(kc) * 128 + (size_t)r * (DDIM * 2) + s * 16; \
        const char* bgp = Bg + (size_t)(kc) * 128 + (size_t)r * (DDIM * 2) + s * 16; \
        CP_ASYNC16(abase2 + off, agp);                                          \
        CP_ASYNC16(bbase2 + off, bgp);                                          \
    } while (0)

    #define STAGE_FULL(bufi, kc) do {                                           \
        STAGE_Q(bufi, kc, 0); STAGE_Q(bufi, kc, 1);                              \
        STAGE_Q(bufi, kc, 2); STAGE_Q(bufi, kc, 3);                              \
    } while (0)

    STAGE_FULL(0, 0); CP_COMMIT();
    STAGE_FULL(1, 1); CP_COMMIT();

    int buf = 0;
    #pragma unroll 1
    for (int kc = 0; kc < NKCH; kc++) {
        if (kc < NKCH - 1) CP_WAIT(1); else CP_WAIT(0);
        __syncthreads();   // stage kc visible; stage (kc-1)%3 fully drained

        int nb = buf + 2; if (nb >= 3) nb -= 3;
        bool do_stage = (kc + 2 < NKCH);

        uint32_t abase = sb + buf * STAGE_BYTES;
        uint32_t bbase = abase + SMEM_B_OFF;

        #pragma unroll
        for (int kk = 0; kk < 4; kk++) {
            uint32_t kb = kk * 32;
            uint32_t afr[2][4];
            ldmx4(afr[0], abase + a_rb0 + ((kb + a_csub) ^ a_xm0));
            ldmx4(afr[1], abase + a_rb1 + ((kb + a_csub) ^ a_xm1));
            uint32_t bfr[8][2];
            #pragma unroll
            for (int ntp = 0; ntp < 4; ntp++) {
                uint32_t r[4];
                ldmx4(r, bbase + b_rb[ntp] + ((kb + b_csub) ^ b_xm[ntp]));
                bfr[2 * ntp][0] = r[0];     bfr[2 * ntp][1] = r[1];
                bfr[2 * ntp + 1][0] = r[2]; bfr[2 * ntp + 1][1] = r[3];
            }
            // quarter-stage of chunk kc+2 in the LDSM->MMA dependency shadow
            if (do_stage) STAGE_Q(nb, kc + 2, kk);
            #pragma unroll
            for (int mt = 0; mt < 2; mt++)
                #pragma unroll
                for (int nt = 0; nt < 8; nt++)
                    mma_bf16(acc[mt][nt], afr[mt], bfr[nt]);
        }
        if (do_stage) CP_COMMIT();
        buf++; if (buf >= 3) buf = 0;
    }
    #undef STAGE_Q
    #undef STAGE_FULL

    // ---- epilogue: fp32 ex2 exp-sum ----
    float ps0 = 0.0f, ps1 = 0.0f;
    #pragma unroll
    for (int mt = 0; mt < 2; mt++)
        #pragma unroll
        for (int nt = 0; nt < 8; nt++)
            #pragma unroll
            for (int i = 0; i < 4; i++) {
                float s = acc[mt][nt][i] * EXP_SCALE;
                float e;
                asm("ex2.approx.ftz.f32 %0, %1;" : "=f"(e) : "f"(s));
                if (i & 1) ps1 += e; else ps0 += e;
            }
    float psum = ps0 + ps1;
    #pragma unroll
    for (int o = 16; o; o >>= 1) psum += __shfl_xor_sync(0xFFFFFFFFu, psum, o);

    __shared__ float red[8];
    if (lane == 0) red[wid] = psum;
    __syncthreads();
    if (tid == 0) {
        double tot = 0.0;
        #pragma unroll
        for (int w = 0; w < 8; w++) tot += (double)red[w];
        g_partials[blockIdx.x] = tot * (double)weight;
    }
}

// ---------------------------------------------------------------------------
// 3) final reduction -> loss scalar
// ---------------------------------------------------------------------------
__global__ void __launch_bounds__(256) finish_kernel(float* __restrict__ out) {
    int t = threadIdx.x;
    double p = 0.0, n = 0.0;
    for (int i = t; i < TOTAL_TILES; i += 256) {
        double v = g_partials[i];
        if (i < NEG_TILES) n += v; else p += v;
    }
    __shared__ double sp[256], sn[256];
    sp[t] = p; sn[t] = n;
    __syncthreads();
    for (int s = 128; s; s >>= 1) {
        if (t < s) { sp[t] += sp[t + s]; sn[t] += sn[t + s]; }
        __syncthreads();
    }
    if (t == 0) {
        double P = sp[0], N = sn[0];
        out[0] = (float)(-log(P / (N + P)));
    }
}

// ---------------------------------------------------------------------------
extern "C" void kernel_launch(void* const* d_in, const int* in_sizes, int n_in,
                              void* d_out, int out_size) {
    const float* zi = (const float*)d_in[0];
    const float* zj = (const float*)d_in[1];

    cudaFuncSetAttribute(gemm_kernel, cudaFuncAttributeMaxDynamicSharedMemorySize,
                         SMEM_DYN_TOTAL);

    norm_kernel<<<2 * N_ROWS / 8, 256>>>(zi, zj);
    gemm_kernel<<<TOTAL_TILES, NTHREADS, SMEM_DYN_TOTAL>>>();
    finish_kernel<<<1, 256>>>((float*)d_out);
}